// round 1
// baseline (speedup 1.0000x reference)
#include <cuda_runtime.h>

#define NV   8192
#define EE   128
#define CNN  512
#define GG   64
#define TMAXX 32

// ---------------- scratch (device globals; no allocation) ----------------
__device__ float g_rowsum[NV];
__device__ float g_v0[EE];
__device__ float g_u[512];
__device__ float g_bt[512];
__device__ float g_cm0[CNN*EE];
__device__ float g_cm1[CNN*EE];
__device__ float g_P[NV*EE];
__device__ float g_xw[NV*512];
__device__ float g_h[NV*EE];
__device__ float g_c[NV*EE];
__device__ float g_v1[NV*EE];
__device__ float g_v2[NV*EE];
__device__ float g_vote[NV];

// ---------------- prep: v0, u = Wih_v[:, :E] @ v0, bias ----------------
__global__ void k_prep(const float* __restrict__ vw, const float* __restrict__ vb,
                       const float* __restrict__ Wih, const float* __restrict__ bih,
                       const float* __restrict__ bhh) {
    __shared__ float v0s[EE];
    int t = threadIdx.x; // 512 threads
    if (t < EE) { float v = vw[t] + vb[t]; g_v0[t] = v; v0s[t] = v; }
    __syncthreads();
    float acc = 0.f;
    #pragma unroll 8
    for (int k = 0; k < EE; k++) acc += v0s[k] * Wih[t*256 + k];
    g_u[t]  = acc;
    g_bt[t] = bih[t] + bhh[t];
}

// ---------------- rowsum of M_vv (256 MB read; HBM bound) ----------------
__global__ void k_rowsum(const float4* __restrict__ M) {
    __shared__ float red[256];
    int row = blockIdx.x;
    int t = threadIdx.x; // 256
    const float4* p = M + (size_t)row * (NV/4);
    float s = 0.f;
    for (int i = t; i < NV/4; i += 256) {
        float4 v = p[i];
        s += (v.x + v.y) + (v.z + v.w);
    }
    red[t] = s; __syncthreads();
    for (int st = 128; st; st >>= 1) {
        if (t < st) red[t] += red[t + st];
        __syncthreads();
    }
    if (t == 0) g_rowsum[row] = red[0];
}

// ---------------- generic 128->128 linear layer (y = x @ W.T + b, opt relu) ----
template<int R, bool RELU>
__global__ void k_mlp(const float* __restrict__ X, const float* __restrict__ W,
                      const float* __restrict__ B, float* __restrict__ Y) {
    __shared__ float Ws[128*65];   // half-K chunk, padded (stride 65) conflict-free
    __shared__ float Xs[R*128];
    int t = threadIdx.x;           // 128
    int row0 = blockIdx.x * R;
    #pragma unroll
    for (int i = 0; i < R; i++) Xs[i*128 + t] = X[(row0+i)*128 + t];
    float acc[R];
    #pragma unroll
    for (int r = 0; r < R; r++) acc[r] = 0.f;
    for (int kc = 0; kc < 128; kc += 64) {
        __syncthreads();
        for (int idx = t; idx < 128*64; idx += 128) {
            int kl = idx & 63, e2 = idx >> 6;      // coalesced read, conflict-free write
            Ws[e2*65 + kl] = W[e2*128 + kc + kl];
        }
        __syncthreads();
        #pragma unroll 8
        for (int kl = 0; kl < 64; kl++) {
            float w = Ws[t*65 + kl];
            #pragma unroll
            for (int r = 0; r < R; r++)
                acc[r] += Xs[r*128 + kc + kl] * w;
        }
    }
    float b = B[t];
    #pragma unroll
    for (int r = 0; r < R; r++) {
        float v = acc[r] + b;
        if (RELU) v = fmaxf(v, 0.f);
        Y[(row0+r)*128 + t] = v;
    }
}

// ---------------- P = M_vc @ CM  ([8192,512]@[512,128]) ----------------
__global__ void k_P(const float* __restrict__ Mvc, const float* __restrict__ CM) {
    __shared__ float Ms[16*512];
    int t = threadIdx.x;  // 128
    int r0 = blockIdx.x * 16;
    const float4* src = (const float4*)(Mvc + (size_t)r0 * 512);
    float4* dst = (float4*)Ms;
    for (int i = t; i < 16*512/4; i += 128) dst[i] = src[i];
    __syncthreads();
    float acc[16];
    #pragma unroll
    for (int r = 0; r < 16; r++) acc[r] = 0.f;
    #pragma unroll 4
    for (int k = 0; k < 512; k++) {
        float c = CM[k*128 + t];           // coalesced across threads, L2-resident
        #pragma unroll
        for (int r = 0; r < 16; r++) acc[r] += Ms[r*512 + k] * c;
    }
    #pragma unroll
    for (int r = 0; r < 16; r++) g_P[(r0+r)*128 + t] = acc[r];
}

// ---- xW = rowsum*u + P @ Wih_v[:,128:].T + (bih+bhh)   ([8192,512]) ----
__global__ void k_xw(const float* __restrict__ Wih) {
    __shared__ float Ps[16*128];
    __shared__ float rs[16];
    int t = threadIdx.x;  // 128
    int r0 = blockIdx.x * 16;
    for (int i = t; i < 16*128; i += 128) Ps[i] = g_P[r0*128 + i];
    if (t < 16) rs[t] = g_rowsum[r0 + t];
    __syncthreads();
    const float4* Ps4 = (const float4*)Ps;
    #pragma unroll
    for (int j = 0; j < 4; j++) {
        int g = t + j*128;
        float u = g_u[g], bt = g_bt[g];
        float acc[16];
        #pragma unroll
        for (int r = 0; r < 16; r++) acc[r] = 0.f;
        const float4* wr = (const float4*)(Wih + g*256 + 128);
        #pragma unroll 4
        for (int kc = 0; kc < 32; kc++) {
            float4 w = wr[kc];
            #pragma unroll
            for (int r = 0; r < 16; r++) {
                float4 p = Ps4[r*32 + kc];
                acc[r] += p.x*w.x + p.y*w.y + p.z*w.z + p.w*w.w;
            }
        }
        #pragma unroll
        for (int r = 0; r < 16; r++)
            g_xw[(size_t)(r0+r)*512 + g] = acc[r] + rs[r]*u + bt;
    }
}

// ---------------- init: h = v0 broadcast, c = 0 ----------------
__global__ void k_init() {
    int idx = blockIdx.x * blockDim.x + threadIdx.x;
    if (idx < NV*EE) { g_h[idx] = g_v0[idx & 127]; g_c[idx] = 0.f; }
}

__device__ __forceinline__ float sigf(float x) { return 1.f / (1.f + __expf(-x)); }

// ---------------- fused LSTM step: gates = xW + h@Whh.T, update h,c ------
__global__ void k_step(const float* __restrict__ Whh) {
    __shared__ float hs[16*128];   // 8 KB
    __shared__ float gs[16*512];   // 32 KB
    int t = threadIdx.x;           // 512
    int r0 = blockIdx.x * 16;
    ((float4*)hs)[t] = ((const float4*)(g_h + (size_t)r0*128))[t];
    __syncthreads();
    float acc[16];
    #pragma unroll
    for (int r = 0; r < 16; r++) acc[r] = 0.f;
    const float4* wr  = (const float4*)(Whh + t*128);
    const float4* hs4 = (const float4*)hs;
    #pragma unroll 4
    for (int kc = 0; kc < 32; kc++) {
        float4 w = wr[kc];
        #pragma unroll
        for (int r = 0; r < 16; r++) {
            float4 h = hs4[r*32 + kc];
            acc[r] += h.x*w.x + h.y*w.y + h.z*w.z + h.w*w.w;
        }
    }
    #pragma unroll
    for (int r = 0; r < 16; r++)
        gs[r*512 + t] = acc[r] + g_xw[(size_t)(r0+r)*512 + t];
    __syncthreads();
    #pragma unroll
    for (int j = 0; j < 4; j++) {
        int idx = t + j*512;
        int r = idx >> 7, e = idx & 127;
        float ig = gs[r*512 +       e];
        float fg = gs[r*512 + 128 + e];
        float gg = gs[r*512 + 256 + e];
        float og = gs[r*512 + 384 + e];
        int gi = (r0 + r)*128 + e;
        float cn = sigf(fg) * g_c[gi] + sigf(ig) * tanhf(gg);
        g_c[gi] = cn;
        g_h[gi] = sigf(og) * tanhf(cn);
    }
}

// ---------------- vote layer 3: dot with W3 row ----------------
__global__ void k_vote3(const float* __restrict__ W3, const float* __restrict__ b3) {
    int warp = (blockIdx.x * blockDim.x + threadIdx.x) >> 5;
    int lane = threadIdx.x & 31;
    if (warp >= NV) return;
    float4 a = ((const float4*)(g_v2 + (size_t)warp*128))[lane];
    float4 b = ((const float4*)W3)[lane];
    float s = a.x*b.x + a.y*b.y + a.z*b.z + a.w*b.w;
    #pragma unroll
    for (int o = 16; o; o >>= 1) s += __shfl_xor_sync(0xFFFFFFFFu, s, o);
    if (lane == 0) g_vote[warp] = s + b3[0];
}

// ---------------- per-graph mean + sigmoid -> out[0:64] ----------------
__global__ void k_final(const int* __restrict__ slice, float* __restrict__ out) {
    __shared__ float red[128];
    int g = blockIdx.x, t = threadIdx.x;  // 128
    int off = 0;
    for (int i = 0; i < g; i++) off += slice[i];
    int cnt = slice[g];
    float s = 0.f;
    for (int i = t; i < cnt; i += 128) s += g_vote[off + i];
    red[t] = s; __syncthreads();
    for (int st = 64; st; st >>= 1) { if (t < st) red[t] += red[t+st]; __syncthreads(); }
    if (t == 0) out[g] = 1.f / (1.f + __expf(-red[0] / (float)cnt));
}

// ---------------- V broadcast + C passthrough -> out[64:] ----------------
__global__ void k_writeout(const float* __restrict__ C, float* __restrict__ out) {
    int idx = blockIdx.x * blockDim.x + threadIdx.x;
    if (idx < NV*EE) {
        out[64 + idx] = g_v0[idx & 127];
    } else {
        int j = idx - NV*EE;
        if (j < CNN*EE) out[64 + NV*EE + j] = C[j];
    }
}

extern "C" void kernel_launch(void* const* d_in, const int* in_sizes, int n_in,
                              void* d_out, int out_size) {
    const float* M_vv   = (const float*)d_in[0];
    const float* M_vc   = (const float*)d_in[1];
    const float* C      = (const float*)d_in[2];
    const int*   slice  = (const int*)  d_in[3];
    const float* vw     = (const float*)d_in[4];
    const float* vb     = (const float*)d_in[5];
    const float* mlpC_W = (const float*)d_in[6];
    const float* mlpC_b = (const float*)d_in[7];
    const float* Wih_v  = (const float*)d_in[10];
    const float* Whh_v  = (const float*)d_in[11];
    const float* bih_v  = (const float*)d_in[12];
    const float* bhh_v  = (const float*)d_in[13];
    const float* vW1    = (const float*)d_in[18];
    const float* vb1    = (const float*)d_in[19];
    const float* vW2    = (const float*)d_in[20];
    const float* vb2    = (const float*)d_in[21];
    const float* vW3    = (const float*)d_in[22];
    const float* vb3    = (const float*)d_in[23];
    float* out = (float*)d_out;

    void *p_cm0, *p_cm1, *p_h, *p_v1, *p_v2;
    cudaGetSymbolAddress(&p_cm0, g_cm0);
    cudaGetSymbolAddress(&p_cm1, g_cm1);
    cudaGetSymbolAddress(&p_h,   g_h);
    cudaGetSymbolAddress(&p_v1,  g_v1);
    cudaGetSymbolAddress(&p_v2,  g_v2);

    k_prep<<<1, 512>>>(vw, vb, Wih_v, bih_v, bhh_v);
    k_rowsum<<<NV, 256>>>((const float4*)M_vv);

    // mlpC(C): 3 layers, 512 rows
    k_mlp<8, true ><<<CNN/8, 128>>>(C,              mlpC_W,           mlpC_b,       (float*)p_cm0);
    k_mlp<8, true ><<<CNN/8, 128>>>((float*)p_cm0,  mlpC_W + 16384,   mlpC_b + 128, (float*)p_cm1);
    k_mlp<8, false><<<CNN/8, 128>>>((float*)p_cm1,  mlpC_W + 32768,   mlpC_b + 256, (float*)p_cm0);

    k_P<<<NV/16, 128>>>(M_vc, (const float*)p_cm0);
    k_xw<<<NV/16, 128>>>(Wih_v);
    k_init<<<(NV*EE + 255)/256, 256>>>();

    for (int s = 0; s < TMAXX; s++)
        k_step<<<NV/16, 512>>>(Whh_v);

    // vote MLP
    k_mlp<16, true><<<NV/16, 128>>>((const float*)p_h,  vW1, vb1, (float*)p_v1);
    k_mlp<16, true><<<NV/16, 128>>>((const float*)p_v1, vW2, vb2, (float*)p_v2);
    k_vote3<<<NV/8, 256>>>(vW3, vb3);

    k_final<<<GG, 128>>>(slice, out);
    k_writeout<<<(NV*EE + CNN*EE + 255)/256, 256>>>(C, out);
}

// round 2
// speedup vs baseline: 3.3869x; 3.3869x over previous
#include <cuda_runtime.h>

#define NV   8192
#define EE   128
#define CNN  512
#define GG   64
#define TMAXX 32

// ---------------- scratch (device globals; no allocation) ----------------
__device__ float g_rowsum[NV];
__device__ float g_v0[EE];
__device__ float g_u[512];
__device__ float g_bt[512];
__device__ float g_cm0[CNN*EE];
__device__ float g_cm1[CNN*EE];
__device__ float g_xw[NV*512];
__device__ float g_h[NV*EE];
__device__ float g_v1[NV*EE];
__device__ float g_v2[NV*EE];
__device__ float g_vote[NV];

// ---------------- helpers ----------------
__device__ __forceinline__ float to_tf32(float x) {
    float r; asm("cvt.rna.tf32.f32 %0, %1;" : "=f"(r) : "f"(x)); return r;
}
__device__ __forceinline__ float tanha(float x) {
    float r; asm("tanh.approx.f32 %0, %1;" : "=f"(r) : "f"(x)); return r;
}
__device__ __forceinline__ float sigf(float x) { return fmaf(tanha(0.5f*x), 0.5f, 0.5f); }

__device__ __forceinline__ void mma_tf32(float* d, const float* a, float b0, float b1) {
    asm volatile(
        "mma.sync.aligned.m16n8k8.row.col.f32.tf32.tf32.f32 "
        "{%0,%1,%2,%3},{%4,%5,%6,%7},{%8,%9},{%0,%1,%2,%3};"
        : "+f"(d[0]), "+f"(d[1]), "+f"(d[2]), "+f"(d[3])
        : "r"(__float_as_uint(a[0])), "r"(__float_as_uint(a[1])),
          "r"(__float_as_uint(a[2])), "r"(__float_as_uint(a[3])),
          "r"(__float_as_uint(b0)),   "r"(__float_as_uint(b1)));
}

// ------- launch 0: rowsum of M_vv + (extra block) prep of v0/u/bias -------
__global__ void k_rowsum_prep(const float4* __restrict__ M,
                              const float* __restrict__ vw, const float* __restrict__ vb,
                              const float* __restrict__ Wih, const float* __restrict__ bih,
                              const float* __restrict__ bhh) {
    if (blockIdx.x == NV) {
        __shared__ float v0s[EE];
        int t = threadIdx.x;  // 256
        if (t < EE) { float v = vw[t] + vb[t]; g_v0[t] = v; v0s[t] = v; }
        __syncthreads();
        for (int gi = t; gi < 512; gi += 256) {
            float acc = 0.f;
            #pragma unroll 8
            for (int k = 0; k < EE; k++) acc += v0s[k] * Wih[gi*256 + k];
            g_u[gi]  = acc;
            g_bt[gi] = bih[gi] + bhh[gi];
        }
        return;
    }
    __shared__ float red[256];
    int row = blockIdx.x;
    int t = threadIdx.x; // 256
    const float4* p = M + (size_t)row * (NV/4);
    float s = 0.f;
    for (int i = t; i < NV/4; i += 256) {
        float4 v = p[i];
        s += (v.x + v.y) + (v.z + v.w);
    }
    red[t] = s; __syncthreads();
    for (int st = 128; st; st >>= 1) {
        if (t < st) red[t] += red[t + st];
        __syncthreads();
    }
    if (t == 0) g_rowsum[row] = red[0];
}

// ---------------- generic 128->128 linear layer (y = x @ W.T + b) ----------
template<int R, bool RELU>
__global__ void k_mlp(const float* __restrict__ X, const float* __restrict__ W,
                      const float* __restrict__ B, float* __restrict__ Y) {
    __shared__ float Ws[128*65];
    __shared__ float Xs[R*128];
    int t = threadIdx.x;           // 128
    int row0 = blockIdx.x * R;
    #pragma unroll
    for (int i = 0; i < R; i++) Xs[i*128 + t] = X[(row0+i)*128 + t];
    float acc[R];
    #pragma unroll
    for (int r = 0; r < R; r++) acc[r] = 0.f;
    for (int kc = 0; kc < 128; kc += 64) {
        __syncthreads();
        for (int idx = t; idx < 128*64; idx += 128) {
            int kl = idx & 63, e2 = idx >> 6;
            Ws[e2*65 + kl] = W[e2*128 + kc + kl];
        }
        __syncthreads();
        #pragma unroll 8
        for (int kl = 0; kl < 64; kl++) {
            float w = Ws[t*65 + kl];
            #pragma unroll
            for (int r = 0; r < R; r++)
                acc[r] += Xs[r*128 + kc + kl] * w;
        }
    }
    float b = B[t];
    #pragma unroll
    for (int r = 0; r < R; r++) {
        float v = acc[r] + b;
        if (RELU) v = fmaxf(v, 0.f);
        Y[(row0+r)*128 + t] = v;
    }
}

// ------- fused: P = M_vc @ CM then xW = rowsum*u + P @ Wih[:,128:].T + bt -------
__global__ void k_Pxw(const float* __restrict__ Mvc, const float* __restrict__ CM,
                      const float* __restrict__ Wih) {
    __shared__ float Ms[16*512];   // 32 KB
    __shared__ float Ps[16*128];   // 8 KB
    __shared__ float rs[16];
    int t = threadIdx.x;  // 128
    int r0 = blockIdx.x * 16;
    {
        const float4* src = (const float4*)(Mvc + (size_t)r0 * 512);
        float4* dst = (float4*)Ms;
        for (int i = t; i < 16*512/4; i += 128) dst[i] = src[i];
        if (t < 16) rs[t] = g_rowsum[r0 + t];
    }
    __syncthreads();
    {
        float acc[16];
        #pragma unroll
        for (int r = 0; r < 16; r++) acc[r] = 0.f;
        #pragma unroll 4
        for (int k = 0; k < 512; k++) {
            float c = CM[k*128 + t];
            #pragma unroll
            for (int r = 0; r < 16; r++) acc[r] += Ms[r*512 + k] * c;
        }
        #pragma unroll
        for (int r = 0; r < 16; r++) Ps[r*128 + t] = acc[r];
    }
    __syncthreads();
    const float4* Ps4 = (const float4*)Ps;
    #pragma unroll
    for (int j = 0; j < 4; j++) {
        int gi = t + j*128;
        float u = g_u[gi], bt = g_bt[gi];
        float acc[16];
        #pragma unroll
        for (int r = 0; r < 16; r++) acc[r] = 0.f;
        const float4* wr = (const float4*)(Wih + gi*256 + 128);
        #pragma unroll 4
        for (int kc = 0; kc < 32; kc++) {
            float4 w = wr[kc];
            #pragma unroll
            for (int r = 0; r < 16; r++) {
                float4 p = Ps4[r*32 + kc];
                acc[r] += p.x*w.x + p.y*w.y + p.z*w.z + p.w*w.w;
            }
        }
        #pragma unroll
        for (int r = 0; r < 16; r++)
            g_xw[(size_t)(r0+r)*512 + gi] = acc[r] + rs[r]*u + bt;
    }
}

// ---------------- persistent 32-step LSTM via tf32 mma.sync ----------------
// Block: 512 threads (16 warps), M=64 rows. Warp w owns e-tile w (cols 8w..8w+7)
// across all 4 m-tiles and all 4 gates (n-tiles at gt*128 + 8w).
// smem: hs[64][132] (tf32 h), xw[64][516] (fp32 gate bias-activations).
// c and accumulators live in registers; per step: 2 barriers, no global traffic
// except Whh B-fragment reads (L2-resident).
#define HS_STRIDE 132
#define XW_STRIDE 516
__global__ __launch_bounds__(512, 1) void k_steps(const float* __restrict__ Whh) {
    extern __shared__ float sm[];
    float* hs = sm;                    // [64][HS_STRIDE]
    float* xw = sm + 64*HS_STRIDE;     // [64][XW_STRIDE]
    int tid = threadIdx.x;
    int w = tid >> 5, lane = tid & 31;
    int g = lane >> 2, t = lane & 3;
    int r0 = blockIdx.x * 64;
    int eb = 8 * w;

    // load xW tile into smem
    for (int i = tid; i < 64*512; i += 512) {
        int r = i >> 9, c = i & 511;
        xw[r*XW_STRIDE + c] = g_xw[(size_t)(r0 + r)*512 + c];
    }
    // init h = v0 broadcast (tf32-rounded)
    for (int i = tid; i < 64*128; i += 512) {
        int r = i >> 7, c = i & 127;
        hs[r*HS_STRIDE + c] = to_tf32(g_v0[c]);
    }
    __syncthreads();

    // Whh row pointers for this warp's 4 gate n-tiles
    const float* wp[4];
    #pragma unroll
    for (int gt = 0; gt < 4; gt++) wp[gt] = Whh + (size_t)(gt*128 + eb + g) * 128;

    float creg[4][4];
    #pragma unroll
    for (int mt = 0; mt < 4; mt++)
        #pragma unroll
        for (int s = 0; s < 4; s++) creg[mt][s] = 0.f;

    for (int step = 0; step < TMAXX; step++) {
        float acc[4][4][4];
        // acc init = xW fragment
        #pragma unroll
        for (int mt = 0; mt < 4; mt++) {
            int row = mt*16 + g;
            #pragma unroll
            for (int gt = 0; gt < 4; gt++) {
                int col = gt*128 + eb + 2*t;
                acc[mt][gt][0] = xw[row*XW_STRIDE + col];
                acc[mt][gt][1] = xw[row*XW_STRIDE + col + 1];
                acc[mt][gt][2] = xw[(row+8)*XW_STRIDE + col];
                acc[mt][gt][3] = xw[(row+8)*XW_STRIDE + col + 1];
            }
        }
        // mma over K=128 in chunks of 8
        #pragma unroll 4
        for (int kc = 0; kc < 16; kc++) {
            int k0 = kc*8;
            float a[4][4];
            #pragma unroll
            for (int mt = 0; mt < 4; mt++) {
                int row = mt*16 + g;
                a[mt][0] = hs[row*HS_STRIDE + k0 + t];
                a[mt][1] = hs[(row+8)*HS_STRIDE + k0 + t];
                a[mt][2] = hs[row*HS_STRIDE + k0 + t + 4];
                a[mt][3] = hs[(row+8)*HS_STRIDE + k0 + t + 4];
            }
            #pragma unroll
            for (int gt = 0; gt < 4; gt++) {
                float b0 = to_tf32(__ldg(wp[gt] + k0 + t));
                float b1 = to_tf32(__ldg(wp[gt] + k0 + t + 4));
                #pragma unroll
                for (int mt = 0; mt < 4; mt++)
                    mma_tf32(acc[mt][gt], a[mt], b0, b1);
            }
        }
        __syncthreads();   // all mma reads of hs done before epilogue overwrites
        // epilogue: LSTM cell update, write new h (tf32) to smem
        #pragma unroll
        for (int mt = 0; mt < 4; mt++) {
            #pragma unroll
            for (int s = 0; s < 4; s++) {
                float ig = acc[mt][0][s];
                float fg = acc[mt][1][s];
                float gg = acc[mt][2][s];
                float og = acc[mt][3][s];
                float cn = sigf(fg) * creg[mt][s] + sigf(ig) * tanha(gg);
                creg[mt][s] = cn;
                float hh = sigf(og) * tanha(cn);
                int row = mt*16 + g + ((s >> 1) ? 8 : 0);
                int col = eb + 2*t + (s & 1);
                hs[row*HS_STRIDE + col] = to_tf32(hh);
            }
        }
        __syncthreads();
    }
    // write final h to global for the vote MLP
    for (int i = tid; i < 64*128; i += 512) {
        int r = i >> 7, c = i & 127;
        g_h[(size_t)(r0 + r)*128 + c] = hs[r*HS_STRIDE + c];
    }
}

// ---------------- vote layer 3: dot with W3 row ----------------
__global__ void k_vote3(const float* __restrict__ W3, const float* __restrict__ b3) {
    int warp = (blockIdx.x * blockDim.x + threadIdx.x) >> 5;
    int lane = threadIdx.x & 31;
    if (warp >= NV) return;
    float4 a = ((const float4*)(g_v2 + (size_t)warp*128))[lane];
    float4 b = ((const float4*)W3)[lane];
    float s = a.x*b.x + a.y*b.y + a.z*b.z + a.w*b.w;
    #pragma unroll
    for (int o = 16; o; o >>= 1) s += __shfl_xor_sync(0xFFFFFFFFu, s, o);
    if (lane == 0) g_vote[warp] = s + b3[0];
}

// ---------------- per-graph mean + sigmoid -> out[0:64] ----------------
__global__ void k_final(const int* __restrict__ slice, float* __restrict__ out) {
    __shared__ float red[128];
    int g = blockIdx.x, t = threadIdx.x;  // 128
    int off = 0;
    for (int i = 0; i < g; i++) off += slice[i];
    int cnt = slice[g];
    float s = 0.f;
    for (int i = t; i < cnt; i += 128) s += g_vote[off + i];
    red[t] = s; __syncthreads();
    for (int st = 64; st; st >>= 1) { if (t < st) red[t] += red[t+st]; __syncthreads(); }
    if (t == 0) out[g] = 1.f / (1.f + __expf(-red[0] / (float)cnt));
}

// ---------------- V broadcast + C passthrough -> out[64:] ----------------
__global__ void k_writeout(const float* __restrict__ C, float* __restrict__ out) {
    int idx = blockIdx.x * blockDim.x + threadIdx.x;
    if (idx < NV*EE) {
        out[64 + idx] = g_v0[idx & 127];
    } else {
        int j = idx - NV*EE;
        if (j < CNN*EE) out[64 + NV*EE + j] = C[j];
    }
}

extern "C" void kernel_launch(void* const* d_in, const int* in_sizes, int n_in,
                              void* d_out, int out_size) {
    const float* M_vv   = (const float*)d_in[0];
    const float* M_vc   = (const float*)d_in[1];
    const float* C      = (const float*)d_in[2];
    const int*   slice  = (const int*)  d_in[3];
    const float* vw     = (const float*)d_in[4];
    const float* vb     = (const float*)d_in[5];
    const float* mlpC_W = (const float*)d_in[6];
    const float* mlpC_b = (const float*)d_in[7];
    const float* Wih_v  = (const float*)d_in[10];
    const float* Whh_v  = (const float*)d_in[11];
    const float* bih_v  = (const float*)d_in[12];
    const float* bhh_v  = (const float*)d_in[13];
    const float* vW1    = (const float*)d_in[18];
    const float* vb1    = (const float*)d_in[19];
    const float* vW2    = (const float*)d_in[20];
    const float* vb2    = (const float*)d_in[21];
    const float* vW3    = (const float*)d_in[22];
    const float* vb3    = (const float*)d_in[23];
    float* out = (float*)d_out;

    void *p_cm0, *p_cm1, *p_h, *p_v1, *p_v2;
    cudaGetSymbolAddress(&p_cm0, g_cm0);
    cudaGetSymbolAddress(&p_cm1, g_cm1);
    cudaGetSymbolAddress(&p_h,   g_h);
    cudaGetSymbolAddress(&p_v1,  g_v1);
    cudaGetSymbolAddress(&p_v2,  g_v2);

    const int STEPS_SMEM = (64*HS_STRIDE + 64*XW_STRIDE) * 4;  // 165888 bytes
    cudaFuncSetAttribute(k_steps, cudaFuncAttributeMaxDynamicSharedMemorySize, STEPS_SMEM);

    // launch 0: rowsum + prep
    k_rowsum_prep<<<NV + 1, 256>>>((const float4*)M_vv, vw, vb, Wih_v, bih_v, bhh_v);

    // launches 1-3: mlpC(C), 512 rows, R=2 -> 256 blocks (latency-friendly)
    k_mlp<2, true ><<<CNN/2, 128>>>(C,             mlpC_W,         mlpC_b,       (float*)p_cm0);
    k_mlp<2, true ><<<CNN/2, 128>>>((float*)p_cm0, mlpC_W + 16384, mlpC_b + 128, (float*)p_cm1);
    k_mlp<2, false><<<CNN/2, 128>>>((float*)p_cm1, mlpC_W + 32768, mlpC_b + 256, (float*)p_cm0);

    // launch 4: fused P + xW
    k_Pxw<<<NV/16, 128>>>(M_vc, (const float*)p_cm0, Wih_v);

    // launch 5: persistent 32-step LSTM (tf32 tensor)  -- profiled by ncu -s 5
    k_steps<<<NV/64, 512, STEPS_SMEM>>>(Whh_v);

    // vote MLP
    k_mlp<16, true><<<NV/16, 128>>>((const float*)p_h,  vW1, vb1, (float*)p_v1);
    k_mlp<16, true><<<NV/16, 128>>>((const float*)p_v1, vW2, vb2, (float*)p_v2);
    k_vote3<<<NV/8, 256>>>(vW3, vb3);

    k_final<<<GG, 128>>>(slice, out);
    k_writeout<<<(NV*EE + CNN*EE + 255)/256, 256>>>(C, out);
}

// round 3
// speedup vs baseline: 4.0302x; 1.1899x over previous
#include <cuda_runtime.h>

#define NV   8192
#define EE   128
#define CNN  512
#define GG   64
#define TMAXX 32

// ---------------- scratch (device globals; no allocation) ----------------
__device__ float g_rowsum[NV];
__device__ float g_v0[EE];
__device__ float g_u[512];
__device__ float g_bt[512];
__device__ float g_cm0[CNN*EE];
__device__ float g_xw[NV*512];
__device__ float g_h[NV*EE];
__device__ float g_v1[NV*EE];
__device__ float g_v2[NV*EE];
__device__ float g_vote[NV];
__device__ float2 g_whhT[32768];   // repacked tf32 Whh fragments (256 KB)

// ---------------- helpers ----------------
__device__ __forceinline__ float to_tf32(float x) {
    float r; asm("cvt.rna.tf32.f32 %0, %1;" : "=f"(r) : "f"(x)); return r;
}
__device__ __forceinline__ float tanha(float x) {
    float r; asm("tanh.approx.f32 %0, %1;" : "=f"(r) : "f"(x)); return r;
}
__device__ __forceinline__ float sigf(float x) { return fmaf(tanha(0.5f*x), 0.5f, 0.5f); }

__device__ __forceinline__ void mma_tf32(float* d, const float* a, float b0, float b1) {
    asm volatile(
        "mma.sync.aligned.m16n8k8.row.col.f32.tf32.tf32.f32 "
        "{%0,%1,%2,%3},{%4,%5,%6,%7},{%8,%9},{%0,%1,%2,%3};"
        : "+f"(d[0]), "+f"(d[1]), "+f"(d[2]), "+f"(d[3])
        : "r"(__float_as_uint(a[0])), "r"(__float_as_uint(a[1])),
          "r"(__float_as_uint(a[2])), "r"(__float_as_uint(a[3])),
          "r"(__float_as_uint(b0)),   "r"(__float_as_uint(b1)));
}

// ------- launch 0: rowsum of M_vv + (extra block) prep of v0/u/bias -------
__global__ void k_rowsum_prep(const float4* __restrict__ M,
                              const float* __restrict__ vw, const float* __restrict__ vb,
                              const float* __restrict__ Wih, const float* __restrict__ bih,
                              const float* __restrict__ bhh) {
    if (blockIdx.x == NV) {
        __shared__ float v0s[EE];
        int t = threadIdx.x;  // 256
        if (t < EE) { float v = vw[t] + vb[t]; g_v0[t] = v; v0s[t] = v; }
        __syncthreads();
        for (int gi = t; gi < 512; gi += 256) {
            float acc = 0.f;
            #pragma unroll 8
            for (int k = 0; k < EE; k++) acc += v0s[k] * Wih[gi*256 + k];
            g_u[gi]  = acc;
            g_bt[gi] = bih[gi] + bhh[gi];
        }
        return;
    }
    __shared__ float red[256];
    int row = blockIdx.x;
    int t = threadIdx.x; // 256
    const float4* p = M + (size_t)row * (NV/4);
    float s = 0.f;
    for (int i = t; i < NV/4; i += 256) {
        float4 v = p[i];
        s += (v.x + v.y) + (v.z + v.w);
    }
    red[t] = s; __syncthreads();
    for (int st = 128; st; st >>= 1) {
        if (t < st) red[t] += red[t + st];
        __syncthreads();
    }
    if (t == 0) g_rowsum[row] = red[0];
}

// ---- launch 1: fused 3-layer mlpC (blocks 0-31) + Whh repack (blocks 32-95) ----
__global__ void k_mlpC_repack(const float* __restrict__ C, const float* __restrict__ W,
                              const float* __restrict__ B, const float* __restrict__ Whh) {
    int t = threadIdx.x;  // 128
    if (blockIdx.x >= 32) {
        // repack Whh into per-warp coalesced tf32 float2 fragments
        int b = blockIdx.x - 32;
        #pragma unroll
        for (int i = 0; i < 4; i++) {
            int o = b*512 + i*128 + t;
            int pos = o & 31, g = pos >> 2, tt = pos & 3;
            int kc = (o >> 5) & 15, gt = (o >> 9) & 3, w = o >> 11;
            int row = gt*128 + w*8 + g;
            float2 v;
            v.x = to_tf32(Whh[row*128 + kc*8 + tt]);
            v.y = to_tf32(Whh[row*128 + kc*8 + tt + 4]);
            g_whhT[o] = v;
        }
        return;
    }
    extern __shared__ float sm[];
    float* Ws = sm;                 // [128][129]
    float* Xa = sm + 128*129;       // [16][128]
    float* Xb = Xa + 16*128;
    int r0 = blockIdx.x * 16;
    #pragma unroll
    for (int r = 0; r < 16; r++) Xa[r*128 + t] = C[(r0+r)*128 + t];
    float* cur = Xa;
    float* nxt = Xb;
    for (int layer = 0; layer < 3; layer++) {
        __syncthreads();
        const float* Wl = W + layer*16384;
        for (int idx = t; idx < 16384; idx += 128) {
            int e = idx >> 7, k = idx & 127;
            Ws[e*129 + k] = Wl[idx];
        }
        __syncthreads();
        float bv = B[layer*128 + t];
        #pragma unroll 2
        for (int r = 0; r < 16; r++) {
            float acc = bv;
            #pragma unroll 8
            for (int k = 0; k < 128; k++) acc += cur[r*128 + k] * Ws[t*129 + k];
            if (layer < 2) {
                nxt[r*128 + t] = fmaxf(acc, 0.f);
            } else {
                g_cm0[(r0+r)*128 + t] = acc;
            }
        }
        float* tmp = cur; cur = nxt; nxt = tmp;
    }
}

// ------- launch 2: P = M_vc @ CM then xW = rowsum*u + P @ Wih[:,128:].T + bt -------
__global__ void k_Pxw(const float* __restrict__ Mvc, const float* __restrict__ CM,
                      const float* __restrict__ Wih) {
    __shared__ float Ms[16*512];   // 32 KB
    __shared__ float Ps[16*128];   // 8 KB
    __shared__ float rs[16];
    int t = threadIdx.x;  // 128
    int r0 = blockIdx.x * 16;
    {
        const float4* src = (const float4*)(Mvc + (size_t)r0 * 512);
        float4* dst = (float4*)Ms;
        for (int i = t; i < 16*512/4; i += 128) dst[i] = src[i];
        if (t < 16) rs[t] = g_rowsum[r0 + t];
    }
    __syncthreads();
    {
        float acc[16];
        #pragma unroll
        for (int r = 0; r < 16; r++) acc[r] = 0.f;
        #pragma unroll 4
        for (int k = 0; k < 512; k++) {
            float c = CM[k*128 + t];
            #pragma unroll
            for (int r = 0; r < 16; r++) acc[r] += Ms[r*512 + k] * c;
        }
        #pragma unroll
        for (int r = 0; r < 16; r++) Ps[r*128 + t] = acc[r];
    }
    __syncthreads();
    const float4* Ps4 = (const float4*)Ps;
    #pragma unroll
    for (int j = 0; j < 4; j++) {
        int gi = t + j*128;
        float u = g_u[gi], bt = g_bt[gi];
        float acc[16];
        #pragma unroll
        for (int r = 0; r < 16; r++) acc[r] = 0.f;
        const float4* wr = (const float4*)(Wih + gi*256 + 128);
        #pragma unroll 4
        for (int kc = 0; kc < 32; kc++) {
            float4 w = wr[kc];
            #pragma unroll
            for (int r = 0; r < 16; r++) {
                float4 p = Ps4[r*32 + kc];
                acc[r] += p.x*w.x + p.y*w.y + p.z*w.z + p.w*w.w;
            }
        }
        #pragma unroll
        for (int r = 0; r < 16; r++)
            g_xw[(size_t)(r0+r)*512 + gi] = acc[r] + rs[r]*u + bt;
    }
}

// ---------------- launch 3: persistent 32-step LSTM via tf32 mma.sync ----------------
// Block: 512 threads (16 warps), M=64 rows. Warp w owns e-tile w (cols 8w..8w+7)
// across all 4 m-tiles and all 4 gates. B fragments come from the repacked
// g_whhT: one coalesced LDG.64 per (gt,kc) per lane, tf32 pre-rounded.
#define HS_STRIDE 132
#define XW_STRIDE 516
__global__ __launch_bounds__(512, 1) void k_steps() {
    extern __shared__ float sm[];
    float* hs = sm;                    // [64][HS_STRIDE]
    float* xw = sm + 64*HS_STRIDE;     // [64][XW_STRIDE]
    int tid = threadIdx.x;
    int w = tid >> 5, lane = tid & 31;
    int g = lane >> 2, t = lane & 3;
    int r0 = blockIdx.x * 64;
    int eb = 8 * w;

    // load xW tile into smem
    for (int i = tid; i < 64*512; i += 512) {
        int r = i >> 9, c = i & 511;
        xw[r*XW_STRIDE + c] = g_xw[(size_t)(r0 + r)*512 + c];
    }
    // init h = v0 broadcast (tf32-rounded)
    for (int i = tid; i < 64*128; i += 512) {
        int r = i >> 7, c = i & 127;
        hs[r*HS_STRIDE + c] = to_tf32(g_v0[c]);
    }
    __syncthreads();

    // per-warp fragment base: lane (g,t) reads float2 at g*4+t
    const float2* wt = g_whhT + w*2048 + (g*4 + t);

    float creg[4][4];
    #pragma unroll
    for (int mt = 0; mt < 4; mt++)
        #pragma unroll
        for (int s = 0; s < 4; s++) creg[mt][s] = 0.f;

    for (int step = 0; step < TMAXX; step++) {
        float acc[4][4][4];
        #pragma unroll
        for (int mt = 0; mt < 4; mt++) {
            int row = mt*16 + g;
            #pragma unroll
            for (int gt = 0; gt < 4; gt++) {
                int col = gt*128 + eb + 2*t;
                acc[mt][gt][0] = xw[row*XW_STRIDE + col];
                acc[mt][gt][1] = xw[row*XW_STRIDE + col + 1];
                acc[mt][gt][2] = xw[(row+8)*XW_STRIDE + col];
                acc[mt][gt][3] = xw[(row+8)*XW_STRIDE + col + 1];
            }
        }
        #pragma unroll 4
        for (int kc = 0; kc < 16; kc++) {
            int k0 = kc*8;
            float a[4][4];
            #pragma unroll
            for (int mt = 0; mt < 4; mt++) {
                int row = mt*16 + g;
                a[mt][0] = hs[row*HS_STRIDE + k0 + t];
                a[mt][1] = hs[(row+8)*HS_STRIDE + k0 + t];
                a[mt][2] = hs[row*HS_STRIDE + k0 + t + 4];
                a[mt][3] = hs[(row+8)*HS_STRIDE + k0 + t + 4];
            }
            #pragma unroll
            for (int gt = 0; gt < 4; gt++) {
                float2 b = __ldg(wt + (gt*16 + kc)*32);
                #pragma unroll
                for (int mt = 0; mt < 4; mt++)
                    mma_tf32(acc[mt][gt], a[mt], b.x, b.y);
            }
        }
        __syncthreads();   // all mma reads of hs done before epilogue overwrites
        #pragma unroll
        for (int mt = 0; mt < 4; mt++) {
            #pragma unroll
            for (int s = 0; s < 4; s++) {
                float ig = acc[mt][0][s];
                float fg = acc[mt][1][s];
                float gg = acc[mt][2][s];
                float og = acc[mt][3][s];
                float cn = sigf(fg) * creg[mt][s] + sigf(ig) * tanha(gg);
                creg[mt][s] = cn;
                float hh = sigf(og) * tanha(cn);
                int row = mt*16 + g + ((s >> 1) ? 8 : 0);
                int col = eb + 2*t + (s & 1);
                hs[row*HS_STRIDE + col] = to_tf32(hh);
            }
        }
        __syncthreads();
    }
    // write final h to global for the vote MLP
    for (int i = tid; i < 64*128; i += 512) {
        int r = i >> 7, c = i & 127;
        g_h[(size_t)(r0 + r)*128 + c] = hs[r*HS_STRIDE + c];
    }
}

// ---------------- generic 128->128 linear layer (y = x @ W.T + b) ----------
template<int R, bool RELU>
__global__ void k_mlp(const float* __restrict__ X, const float* __restrict__ W,
                      const float* __restrict__ B, float* __restrict__ Y) {
    __shared__ float Ws[128*65];
    __shared__ float Xs[R*128];
    int t = threadIdx.x;           // 128
    int row0 = blockIdx.x * R;
    #pragma unroll
    for (int i = 0; i < R; i++) Xs[i*128 + t] = X[(row0+i)*128 + t];
    float acc[R];
    #pragma unroll
    for (int r = 0; r < R; r++) acc[r] = 0.f;
    for (int kc = 0; kc < 128; kc += 64) {
        __syncthreads();
        for (int idx = t; idx < 128*64; idx += 128) {
            int kl = idx & 63, e2 = idx >> 6;
            Ws[e2*65 + kl] = W[e2*128 + kc + kl];
        }
        __syncthreads();
        #pragma unroll 8
        for (int kl = 0; kl < 64; kl++) {
            float w = Ws[t*65 + kl];
            #pragma unroll
            for (int r = 0; r < R; r++)
                acc[r] += Xs[r*128 + kc + kl] * w;
        }
    }
    float b = B[t];
    #pragma unroll
    for (int r = 0; r < R; r++) {
        float v = acc[r] + b;
        if (RELU) v = fmaxf(v, 0.f);
        Y[(row0+r)*128 + t] = v;
    }
}

// ---------------- vote layer 3: dot with W3 row ----------------
__global__ void k_vote3(const float* __restrict__ W3, const float* __restrict__ b3) {
    int warp = (blockIdx.x * blockDim.x + threadIdx.x) >> 5;
    int lane = threadIdx.x & 31;
    if (warp >= NV) return;
    float4 a = ((const float4*)(g_v2 + (size_t)warp*128))[lane];
    float4 b = ((const float4*)W3)[lane];
    float s = a.x*b.x + a.y*b.y + a.z*b.z + a.w*b.w;
    #pragma unroll
    for (int o = 16; o; o >>= 1) s += __shfl_xor_sync(0xFFFFFFFFu, s, o);
    if (lane == 0) g_vote[warp] = s + b3[0];
}

// ---------------- per-graph mean + sigmoid -> out[0:64] ----------------
__global__ void k_final(const int* __restrict__ slice, float* __restrict__ out) {
    __shared__ float red[128];
    int g = blockIdx.x, t = threadIdx.x;  // 128
    int off = 0;
    for (int i = 0; i < g; i++) off += slice[i];
    int cnt = slice[g];
    float s = 0.f;
    for (int i = t; i < cnt; i += 128) s += g_vote[off + i];
    red[t] = s; __syncthreads();
    for (int st = 64; st; st >>= 1) { if (t < st) red[t] += red[t+st]; __syncthreads(); }
    if (t == 0) out[g] = 1.f / (1.f + __expf(-red[0] / (float)cnt));
}

// ---------------- V broadcast + C passthrough -> out[64:] ----------------
__global__ void k_writeout(const float* __restrict__ C, float* __restrict__ out) {
    int idx = blockIdx.x * blockDim.x + threadIdx.x;
    if (idx < NV*EE) {
        out[64 + idx] = g_v0[idx & 127];
    } else {
        int j = idx - NV*EE;
        if (j < CNN*EE) out[64 + NV*EE + j] = C[j];
    }
}

extern "C" void kernel_launch(void* const* d_in, const int* in_sizes, int n_in,
                              void* d_out, int out_size) {
    const float* M_vv   = (const float*)d_in[0];
    const float* M_vc   = (const float*)d_in[1];
    const float* C      = (const float*)d_in[2];
    const int*   slice  = (const int*)  d_in[3];
    const float* vw     = (const float*)d_in[4];
    const float* vb     = (const float*)d_in[5];
    const float* mlpC_W = (const float*)d_in[6];
    const float* mlpC_b = (const float*)d_in[7];
    const float* Wih_v  = (const float*)d_in[10];
    const float* Whh_v  = (const float*)d_in[11];
    const float* bih_v  = (const float*)d_in[12];
    const float* bhh_v  = (const float*)d_in[13];
    const float* vW1    = (const float*)d_in[18];
    const float* vb1    = (const float*)d_in[19];
    const float* vW2    = (const float*)d_in[20];
    const float* vb2    = (const float*)d_in[21];
    const float* vW3    = (const float*)d_in[22];
    const float* vb3    = (const float*)d_in[23];
    float* out = (float*)d_out;

    void *p_cm0, *p_h, *p_v1, *p_v2;
    cudaGetSymbolAddress(&p_cm0, g_cm0);
    cudaGetSymbolAddress(&p_h,   g_h);
    cudaGetSymbolAddress(&p_v1,  g_v1);
    cudaGetSymbolAddress(&p_v2,  g_v2);

    const int STEPS_SMEM = (64*HS_STRIDE + 64*XW_STRIDE) * 4;  // 165888 bytes
    cudaFuncSetAttribute(k_steps, cudaFuncAttributeMaxDynamicSharedMemorySize, STEPS_SMEM);
    const int MLPC_SMEM = (128*129 + 2*16*128) * 4;            // 82432 bytes
    cudaFuncSetAttribute(k_mlpC_repack, cudaFuncAttributeMaxDynamicSharedMemorySize, MLPC_SMEM);

    // 0: rowsum + prep
    k_rowsum_prep<<<NV + 1, 256>>>((const float4*)M_vv, vw, vb, Wih_v, bih_v, bhh_v);
    // 1: fused mlpC + Whh repack
    k_mlpC_repack<<<96, 128, MLPC_SMEM>>>(C, mlpC_W, mlpC_b, Whh_v);
    // 2: fused P + xW
    k_Pxw<<<NV/16, 128>>>(M_vc, (const float*)p_cm0, Wih_v);
    // 3: persistent 32-step LSTM (tf32 tensor)
    k_steps<<<NV/64, 512, STEPS_SMEM>>>();
    // 4-6: vote MLP
    k_mlp<8, true><<<NV/8, 128>>>((const float*)p_h,  vW1, vb1, (float*)p_v1);
    k_mlp<8, true><<<NV/8, 128>>>((const float*)p_v1, vW2, vb2, (float*)p_v2);
    k_vote3<<<NV/8, 256>>>(vW3, vb3);
    // 7-8: reduce + outputs
    k_final<<<GG, 128>>>(slice, out);
    k_writeout<<<(NV*EE + CNN*EE + 255)/256, 256>>>(C, out);
}